// round 13
// baseline (speedup 1.0000x reference)
#include <cuda_runtime.h>
#include <cuda_fp16.h>
#include <cstdint>

#define N_NODES 50000
#define M_PAD   50048      // 391 * 128
#define N_EDGES 800000
#define NFEAT   512
#define NHID    256
#define NCLASS  64
#define NBLK_SCAN 196      // ceil(50000/256)

// ---------------- scratch (static device globals; no runtime allocation) ----
__device__ __align__(256) __half g_B1[(size_t)NHID * NFEAT];     // [n][k] = fp16(W1[k][n])
__device__ __align__(256) __half g_B2[(size_t)NCLASS * NHID];    // [n][k] = fp16(W2[k][n])
__device__ __align__(256) __half g_XW1[(size_t)N_NODES * NHID];  // 26 MB
__device__ __align__(256) __half g_HW2[(size_t)M_PAD * NCLASS];  // 6.4 MB
__device__ int   g_counts [N_NODES];
__device__ int   g_row_ptr[N_NODES + 1];
__device__ int   g_incl   [N_NODES];       // block-local inclusive scan
__device__ int   g_blksum [256];
__device__ int   g_perm   [N_EDGES];
__device__ int   g_src_sorted[N_EDGES];
__device__ float g_w_sorted  [N_EDGES];

// ---------------- helpers ---------------------------------------------------
__device__ __forceinline__ uint32_t smem_u32(const void* p) {
    uint32_t a;
    asm("{ .reg .u64 t; cvta.to.shared.u64 t, %1; cvt.u32.u64 %0, t; }"
        : "=r"(a) : "l"(p));
    return a;
}
__device__ __forceinline__ uint32_t pack_h2(__half a, __half b) {
    __half2 p(a, b);
    return *(uint32_t*)&p;
}

// ---------------- CSR build -------------------------------------------------
__global__ void zero_counts_k() {
    int i = blockIdx.x * blockDim.x + threadIdx.x;
    if (i * 4 < N_NODES) *(int4*)(g_counts + i * 4) = make_int4(0, 0, 0, 0);
}

// histogram + record each edge's within-node rank (perm)
__global__ void hist_k(const int4* __restrict__ edst4) {
    int i = blockIdx.x * blockDim.x + threadIdx.x;
    if (i < N_EDGES / 4) {
        int4 d = __ldg(&edst4[i]);
        int p0 = atomicAdd(&g_counts[d.x], 1);
        int p1 = atomicAdd(&g_counts[d.y], 1);
        int p2 = atomicAdd(&g_counts[d.z], 1);
        int p3 = atomicAdd(&g_counts[d.w], 1);
        *(int4*)(g_perm + i * 4) = make_int4(p0, p1, p2, p3);
    }
}

// 3-phase parallel scan of g_counts -> g_row_ptr (exclusive)
__global__ __launch_bounds__(256) void scan_a_k() {
    __shared__ int sh[256];
    int b = blockIdx.x, t = threadIdx.x;
    int i = b * 256 + t;
    int v = (i < N_NODES) ? g_counts[i] : 0;
    sh[t] = v;
    __syncthreads();
    for (int off = 1; off < 256; off <<= 1) {
        int u = (t >= off) ? sh[t - off] : 0;
        __syncthreads();
        sh[t] += u;
        __syncthreads();
    }
    if (i < N_NODES) g_incl[i] = sh[t];
    if (t == 255) g_blksum[b] = sh[255];
}

__global__ __launch_bounds__(256) void scan_b_k() {
    __shared__ int sh[256];
    int t = threadIdx.x;
    sh[t] = (t < NBLK_SCAN) ? g_blksum[t] : 0;
    __syncthreads();
    for (int off = 1; off < 256; off <<= 1) {
        int u = (t >= off) ? sh[t - off] : 0;
        __syncthreads();
        sh[t] += u;
        __syncthreads();
    }
    g_blksum[t] = sh[t];   // inclusive
}

__global__ __launch_bounds__(256) void scan_c_k() {
    int b = blockIdx.x, t = threadIdx.x;
    int i = b * 256 + t;
    if (i < N_NODES) {
        int off = (b == 0) ? 0 : g_blksum[b - 1];
        int incl = g_incl[i] + off;
        g_row_ptr[i] = incl - g_counts[i];
        if (i == N_NODES - 1) g_row_ptr[N_NODES] = incl;
    }
}

// atomic-free scatter using perm
__global__ void scatter_k(const int4* __restrict__ esrc4,
                          const int4* __restrict__ edst4,
                          const float4* __restrict__ ew4) {
    int i = blockIdx.x * blockDim.x + threadIdx.x;
    if (i < N_EDGES / 4) {
        int4   sv = __ldg(&esrc4[i]);
        int4   dv = __ldg(&edst4[i]);
        float4 wv = __ldg(&ew4[i]);
        int4   pv = *(const int4*)(g_perm + i * 4);
        int p0 = __ldg(&g_row_ptr[dv.x]) + pv.x;
        int p1 = __ldg(&g_row_ptr[dv.y]) + pv.y;
        int p2 = __ldg(&g_row_ptr[dv.z]) + pv.z;
        int p3 = __ldg(&g_row_ptr[dv.w]) + pv.w;
        g_src_sorted[p0] = sv.x; g_w_sorted[p0] = wv.x;
        g_src_sorted[p1] = sv.y; g_w_sorted[p1] = wv.y;
        g_src_sorted[p2] = sv.z; g_w_sorted[p2] = wv.z;
        g_src_sorted[p3] = sv.w; g_w_sorted[p3] = wv.w;
    }
}

// ---------------- weight conversions (merged) --------------------------------
__global__ void conv_w_k(const float* __restrict__ W1,
                         const float* __restrict__ W2) {
    int i = blockIdx.x * blockDim.x + threadIdx.x;
    if (i < NFEAT * NHID) {
        int k = i / NHID, n = i - k * NHID;
        g_B1[(size_t)n * NFEAT + k] = __float2half(W1[i]);
    } else if (i < NFEAT * NHID + NHID * NCLASS) {
        int j = i - NFEAT * NHID;
        int k = j / NCLASS, n = j - k * NCLASS;
        g_B2[(size_t)n * NHID + k] = __float2half(W2[j]);
    }
}

// ---------------- GEMM1 fused: XW1 = x @ W1, fp16 single-term ---------------
// BM=128, BN=256 (all columns), 512 threads = 16 warps (4x4), warp tile 32x64.
__global__ __launch_bounds__(512, 1) void gemm1_fused_k(const float* __restrict__ x,
                                                        const __half* __restrict__ B1,
                                                        __half* __restrict__ C) {
    constexpr int STRIDE_B = 80;
    constexpr int NCH = NFEAT / 32;   // 16
    extern __shared__ char smem[];
    uint32_t sa = smem_u32(smem);

    int tid = threadIdx.x, warp = tid >> 5, lane = tid & 31;
    int m0 = blockIdx.x * 128;
    int wm = warp & 3, wn = warp >> 2;
    int wm0 = wm * 32, wn0 = wn * 64;

    int r = tid >> 2, q = tid & 3;
    bool rowok = (m0 + r) < N_NODES;
    const float* xrow = x + (size_t)(m0 + r) * NFEAT + q * 8;

    const char* Bgl = (const char*)B1;

    auto load_B = [&](int c, int buf) {
        uint32_t bb = sa + 10240 + buf * 20480;
#pragma unroll
        for (int u = 0; u < 2; u++) {
            int idx = u * 512 + tid;
            int row = idx >> 2, qq = idx & 3;
            uint32_t dst = bb + row * STRIDE_B + qq * 16;
            const void* src = Bgl + (size_t)row * 1024 + c * 64 + qq * 16;
            asm volatile("cp.async.cg.shared.global [%0], [%1], 16;"
                         :: "r"(dst), "l"(src));
        }
        asm volatile("cp.async.commit_group;");
    };

    float4 pf[2];
#pragma unroll
    for (int j = 0; j < 2; j++)
        pf[j] = rowok ? *(const float4*)(xrow + j * 4)
                      : make_float4(0.f, 0.f, 0.f, 0.f);
    load_B(0, 0);

    float acc[2][8][4];
#pragma unroll
    for (int i = 0; i < 2; i++)
#pragma unroll
        for (int j = 0; j < 8; j++)
#pragma unroll
            for (int p = 0; p < 4; p++) acc[i][j][p] = 0.f;

    for (int c = 0; c < NCH; c++) {
        {
            char* base = smem + r * STRIDE_B + q * 16;
            __half h[8];
#pragma unroll
            for (int j = 0; j < 2; j++) {
                float4 v = pf[j];
                h[j*4+0] = __float2half(v.x);
                h[j*4+1] = __float2half(v.y);
                h[j*4+2] = __float2half(v.z);
                h[j*4+3] = __float2half(v.w);
            }
            uint4 hv = make_uint4(pack_h2(h[0],h[1]), pack_h2(h[2],h[3]),
                                  pack_h2(h[4],h[5]), pack_h2(h[6],h[7]));
            *(uint4*)base = hv;
        }
        if (c + 1 < NCH) {
#pragma unroll
            for (int j = 0; j < 2; j++)
                pf[j] = rowok ? *(const float4*)(xrow + (c + 1) * 32 + j * 4)
                              : make_float4(0.f, 0.f, 0.f, 0.f);
            load_B(c + 1, (c + 1) & 1);
            asm volatile("cp.async.wait_group 1;");
        } else {
            asm volatile("cp.async.wait_group 0;");
        }
        __syncthreads();

        uint32_t aH = sa;
        uint32_t bH = sa + 10240 + (c & 1) * 20480;
#pragma unroll
        for (int kk = 0; kk < 2; kk++) {
            uint32_t af[2][4];
#pragma unroll
            for (int mt = 0; mt < 2; mt++) {
                uint32_t addr = aH + (wm0 + mt * 16 + (lane & 15)) * STRIDE_B
                              + kk * 32 + (lane >> 4) * 16;
                asm volatile(
                    "ldmatrix.sync.aligned.m8n8.x4.shared.b16 {%0,%1,%2,%3}, [%4];"
                    : "=r"(af[mt][0]), "=r"(af[mt][1]),
                      "=r"(af[mt][2]), "=r"(af[mt][3]) : "r"(addr));
            }
#pragma unroll
            for (int nh = 0; nh < 2; nh++) {
                uint32_t bf[4][2];
#pragma unroll
                for (int nb = 0; nb < 2; nb++) {
                    int nrow = wn0 + nh * 32 + nb * 16
                             + (lane & 7) + ((lane >> 4) & 1) * 8;
                    int khalf = (lane >> 3) & 1;
                    uint32_t adH = bH + nrow * STRIDE_B + kk * 32 + khalf * 16;
                    asm volatile(
                        "ldmatrix.sync.aligned.m8n8.x4.shared.b16 {%0,%1,%2,%3}, [%4];"
                        : "=r"(bf[nb * 2][0]), "=r"(bf[nb * 2][1]),
                          "=r"(bf[nb * 2 + 1][0]), "=r"(bf[nb * 2 + 1][1])
                        : "r"(adH));
                }
#pragma unroll
                for (int mt = 0; mt < 2; mt++)
#pragma unroll
                    for (int nt = 0; nt < 4; nt++)
                        asm volatile(
                            "mma.sync.aligned.m16n8k16.row.col.f32.f16.f16.f32 "
                            "{%0,%1,%2,%3}, {%4,%5,%6,%7}, {%8,%9}, {%0,%1,%2,%3};"
                            : "+f"(acc[mt][nh*4+nt][0]), "+f"(acc[mt][nh*4+nt][1]),
                              "+f"(acc[mt][nh*4+nt][2]), "+f"(acc[mt][nh*4+nt][3])
                            : "r"(af[mt][0]), "r"(af[mt][1]),
                              "r"(af[mt][2]), "r"(af[mt][3]),
                              "r"(bf[nt][0]), "r"(bf[nt][1]));
            }
        }
        __syncthreads();
    }

#pragma unroll
    for (int mt = 0; mt < 2; mt++) {
        int r0 = m0 + wm0 + mt * 16 + (lane >> 2);
#pragma unroll
        for (int nt = 0; nt < 8; nt++) {
            int cc = wn0 + nt * 8 + (lane & 3) * 2;
            if (r0 < N_NODES)
                *(uint32_t*)(C + (size_t)r0 * NHID + cc) =
                    pack_h2(__float2half(acc[mt][nt][0]),
                            __float2half(acc[mt][nt][1]));
            if (r0 + 8 < N_NODES)
                *(uint32_t*)(C + (size_t)(r0 + 8) * NHID + cc) =
                    pack_h2(__float2half(acc[mt][nt][2]),
                            __float2half(acc[mt][nt][3]));
        }
    }
}

// ---------------- fused SpMM1 + GEMM2 ---------------------------------------
// Block = 128 nodes. Phase 1: gather H = relu(A@XW1 + b1) into smem (fp16).
// Phase 2: HW2 tile = H(smem) @ B2^T(smem).  Row stride 528 B (16*33) =>
// ldmatrix conflict-free. smem: H 128*528=67584, B 64*528=33792 -> 101376 B.
__global__ __launch_bounds__(256, 1) void spmm1_gemm2_k(const float* __restrict__ b1,
                                                        const __half* __restrict__ B2,
                                                        __half* __restrict__ C) {
    constexpr int SH = 528;
    constexpr int H_BYTES = 128 * SH;
    extern __shared__ char smem[];
    uint32_t sa = smem_u32(smem);
    uint32_t sH = sa, sB = sa + H_BYTES;

    int tid = threadIdx.x, warp = tid >> 5, lane = tid & 31;
    int m0 = blockIdx.x * 128;

    // load B2 (64 x 512B) via cp.async: 8 x 16B per thread
#pragma unroll
    for (int u = 0; u < 8; u++) {
        int idx = u * 256 + tid;
        int row = idx >> 5, ch = idx & 31;
        uint32_t dst = sB + row * SH + ch * 16;
        const void* src = (const char*)B2 + (size_t)row * 512 + ch * 16;
        asm volatile("cp.async.cg.shared.global [%0], [%1], 16;"
                     :: "r"(dst), "l"(src));
    }
    asm volatile("cp.async.commit_group;");

    // phase 1: gather. 4 groups of 64 threads; 32 nodes per group.
    int g = tid >> 6, ft = tid & 63, fb = ft * 4;
    float4 bb = __ldg((const float4*)(b1 + fb));
    for (int it = 0; it < 32; it++) {
        int local = it * 4 + g;
        int node = m0 + local;
        uint2 hv;
        if (node < N_NODES) {
            int s = g_row_ptr[node], e = g_row_ptr[node + 1];
            float a0 = 0.f, a1 = 0.f, a2 = 0.f, a3 = 0.f;
            int i = s;
            for (; i + 2 <= e; i += 2) {
                int   s0 = __ldg(&g_src_sorted[i]);
                int   s1 = __ldg(&g_src_sorted[i + 1]);
                float w0 = __ldg(&g_w_sorted[i]);
                float w1 = __ldg(&g_w_sorted[i + 1]);
                uint2 u0 = __ldg((const uint2*)(g_XW1 + (size_t)s0 * NHID + fb));
                uint2 u1 = __ldg((const uint2*)(g_XW1 + (size_t)s1 * NHID + fb));
                float2 p0 = __half22float2(*(__half2*)&u0.x);
                float2 p1 = __half22float2(*(__half2*)&u0.y);
                a0 += w0 * p0.x; a1 += w0 * p0.y; a2 += w0 * p1.x; a3 += w0 * p1.y;
                float2 q0 = __half22float2(*(__half2*)&u1.x);
                float2 q1 = __half22float2(*(__half2*)&u1.y);
                a0 += w1 * q0.x; a1 += w1 * q0.y; a2 += w1 * q1.x; a3 += w1 * q1.y;
            }
            if (i < e) {
                int   s0 = __ldg(&g_src_sorted[i]);
                float w0 = __ldg(&g_w_sorted[i]);
                uint2 u0 = __ldg((const uint2*)(g_XW1 + (size_t)s0 * NHID + fb));
                float2 p0 = __half22float2(*(__half2*)&u0.x);
                float2 p1 = __half22float2(*(__half2*)&u0.y);
                a0 += w0 * p0.x; a1 += w0 * p0.y; a2 += w0 * p1.x; a3 += w0 * p1.y;
            }
            float v0 = fmaxf(a0 + bb.x, 0.f);
            float v1 = fmaxf(a1 + bb.y, 0.f);
            float v2 = fmaxf(a2 + bb.z, 0.f);
            float v3 = fmaxf(a3 + bb.w, 0.f);
            hv = make_uint2(pack_h2(__float2half(v0), __float2half(v1)),
                            pack_h2(__float2half(v2), __float2half(v3)));
        } else {
            hv = make_uint2(0u, 0u);
        }
        *(uint2*)(smem + local * SH + fb * 2) = hv;
    }
    asm volatile("cp.async.wait_group 0;");
    __syncthreads();

    // phase 2: mma. 8 warps: 4 x 2, warp tile 32 x 32, K=256 -> 16 k16 steps.
    int wm = warp & 3, wn = warp >> 2;
    int wm0 = wm * 32, wn0 = wn * 32;

    float acc[2][4][4];
#pragma unroll
    for (int i = 0; i < 2; i++)
#pragma unroll
        for (int j = 0; j < 4; j++)
#pragma unroll
            for (int p = 0; p < 4; p++) acc[i][j][p] = 0.f;

#pragma unroll
    for (int ks = 0; ks < 16; ks++) {
        uint32_t af[2][4];
#pragma unroll
        for (int mt = 0; mt < 2; mt++) {
            uint32_t addr = sH + (wm0 + mt * 16 + (lane & 15)) * SH
                          + ks * 32 + (lane >> 4) * 16;
            asm volatile(
                "ldmatrix.sync.aligned.m8n8.x4.shared.b16 {%0,%1,%2,%3}, [%4];"
                : "=r"(af[mt][0]), "=r"(af[mt][1]),
                  "=r"(af[mt][2]), "=r"(af[mt][3]) : "r"(addr));
        }
        uint32_t bf[4][2];
#pragma unroll
        for (int nb = 0; nb < 2; nb++) {
            int nrow = wn0 + nb * 16 + (lane & 7) + ((lane >> 4) & 1) * 8;
            int khalf = (lane >> 3) & 1;
            uint32_t addr = sB + nrow * SH + ks * 32 + khalf * 16;
            asm volatile(
                "ldmatrix.sync.aligned.m8n8.x4.shared.b16 {%0,%1,%2,%3}, [%4];"
                : "=r"(bf[nb * 2][0]), "=r"(bf[nb * 2][1]),
                  "=r"(bf[nb * 2 + 1][0]), "=r"(bf[nb * 2 + 1][1])
                : "r"(addr));
        }
#pragma unroll
        for (int mt = 0; mt < 2; mt++)
#pragma unroll
            for (int nt = 0; nt < 4; nt++)
                asm volatile(
                    "mma.sync.aligned.m16n8k16.row.col.f32.f16.f16.f32 "
                    "{%0,%1,%2,%3}, {%4,%5,%6,%7}, {%8,%9}, {%0,%1,%2,%3};"
                    : "+f"(acc[mt][nt][0]), "+f"(acc[mt][nt][1]),
                      "+f"(acc[mt][nt][2]), "+f"(acc[mt][nt][3])
                    : "r"(af[mt][0]), "r"(af[mt][1]),
                      "r"(af[mt][2]), "r"(af[mt][3]),
                      "r"(bf[nt][0]), "r"(bf[nt][1]));
    }

#pragma unroll
    for (int mt = 0; mt < 2; mt++) {
        int r0 = m0 + wm0 + mt * 16 + (lane >> 2);
#pragma unroll
        for (int nt = 0; nt < 4; nt++) {
            int cc = wn0 + nt * 8 + (lane & 3) * 2;
            *(uint32_t*)(C + (size_t)r0 * NCLASS + cc) =
                pack_h2(__float2half(acc[mt][nt][0]),
                        __float2half(acc[mt][nt][1]));
            *(uint32_t*)(C + (size_t)(r0 + 8) * NCLASS + cc) =
                pack_h2(__float2half(acc[mt][nt][2]),
                        __float2half(acc[mt][nt][3]));
        }
    }
}

// ---------------- SpMM layer 2 fused with bias + log_softmax ----------------
__global__ __launch_bounds__(256) void spmm2_lsm_k(const float* __restrict__ b2,
                                                   float* __restrict__ out) {
    int t = threadIdx.x;
    int node = blockIdx.x * 16 + (t >> 4);
    int fb = (t & 15) * 4;
    int s = g_row_ptr[node], e = g_row_ptr[node + 1];

    float a0 = 0.f, a1 = 0.f, a2 = 0.f, a3 = 0.f;
    int i = s;
    for (; i + 2 <= e; i += 2) {
        int   s0 = __ldg(&g_src_sorted[i]);
        int   s1 = __ldg(&g_src_sorted[i + 1]);
        float w0 = __ldg(&g_w_sorted[i]);
        float w1 = __ldg(&g_w_sorted[i + 1]);
        uint2 u0 = __ldg((const uint2*)(g_HW2 + (size_t)s0 * NCLASS + fb));
        uint2 u1 = __ldg((const uint2*)(g_HW2 + (size_t)s1 * NCLASS + fb));
        float2 p0 = __half22float2(*(__half2*)&u0.x);
        float2 p1 = __half22float2(*(__half2*)&u0.y);
        a0 += w0 * p0.x; a1 += w0 * p0.y; a2 += w0 * p1.x; a3 += w0 * p1.y;
        float2 q0 = __half22float2(*(__half2*)&u1.x);
        float2 q1 = __half22float2(*(__half2*)&u1.y);
        a0 += w1 * q0.x; a1 += w1 * q0.y; a2 += w1 * q1.x; a3 += w1 * q1.y;
    }
    if (i < e) {
        int   s0 = __ldg(&g_src_sorted[i]);
        float w0 = __ldg(&g_w_sorted[i]);
        uint2 u0 = __ldg((const uint2*)(g_HW2 + (size_t)s0 * NCLASS + fb));
        float2 p0 = __half22float2(*(__half2*)&u0.x);
        float2 p1 = __half22float2(*(__half2*)&u0.y);
        a0 += w0 * p0.x; a1 += w0 * p0.y; a2 += w0 * p1.x; a3 += w0 * p1.y;
    }
    float4 bb = __ldg((const float4*)(b2 + fb));
    float4 lg = make_float4(a0 + bb.x, a1 + bb.y, a2 + bb.z, a3 + bb.w);

    float m = fmaxf(fmaxf(lg.x, lg.y), fmaxf(lg.z, lg.w));
#pragma unroll
    for (int o = 8; o > 0; o >>= 1)
        m = fmaxf(m, __shfl_xor_sync(0xffffffffu, m, o));

    float ex = __expf(lg.x - m) + __expf(lg.y - m)
             + __expf(lg.z - m) + __expf(lg.w - m);
#pragma unroll
    for (int o = 8; o > 0; o >>= 1)
        ex += __shfl_xor_sync(0xffffffffu, ex, o);

    float lz = m + __logf(ex);
    float4 rr = make_float4(lg.x - lz, lg.y - lz, lg.z - lz, lg.w - lz);
    *(float4*)(out + (size_t)node * NCLASS + fb) = rr;
}

// ---------------- launch ----------------------------------------------------
extern "C" void kernel_launch(void* const* d_in, const int* in_sizes, int n_in,
                              void* d_out, int out_size) {
    const float* x    = (const float*)d_in[0];
    const float* W1   = (const float*)d_in[1];
    const float* b1   = (const float*)d_in[2];
    const float* W2   = (const float*)d_in[3];
    const float* b2   = (const float*)d_in[4];
    const float* ew   = (const float*)d_in[5];
    const int*   esrc = (const int*)d_in[6];
    const int*   edst = (const int*)d_in[7];
    float* out = (float*)d_out;

    __half *dB1, *dB2, *dXW1, *dHW2;
    cudaGetSymbolAddress((void**)&dB1, g_B1);
    cudaGetSymbolAddress((void**)&dB2, g_B2);
    cudaGetSymbolAddress((void**)&dXW1, g_XW1);
    cudaGetSymbolAddress((void**)&dHW2, g_HW2);

    const int SMEM_G1 = 10240 + 2 * 20480;      // 51200
    const int SMEM_SG = 128 * 528 + 64 * 528;   // 101376
    static bool s_init = false;
    static cudaStream_t s_csr;
    static cudaEvent_t ev_root, ev_csr;
    if (!s_init) {
        cudaFuncSetAttribute(gemm1_fused_k,
                             cudaFuncAttributeMaxDynamicSharedMemorySize, SMEM_G1);
        cudaFuncSetAttribute(spmm1_gemm2_k,
                             cudaFuncAttributeMaxDynamicSharedMemorySize, SMEM_SG);
        cudaStreamCreateWithFlags(&s_csr, cudaStreamNonBlocking);
        cudaEventCreateWithFlags(&ev_root, cudaEventDisableTiming);
        cudaEventCreateWithFlags(&ev_csr, cudaEventDisableTiming);
        s_init = true;
    }

    // fork: CSR build on side stream
    cudaEventRecord(ev_root, 0);
    cudaStreamWaitEvent(s_csr, ev_root, 0);
    zero_counts_k<<<(N_NODES / 4 + 255) / 256, 256, 0, s_csr>>>();
    hist_k<<<(N_EDGES / 4 + 255) / 256, 256, 0, s_csr>>>((const int4*)edst);
    scan_a_k<<<NBLK_SCAN, 256, 0, s_csr>>>();
    scan_b_k<<<1, 256, 0, s_csr>>>();
    scan_c_k<<<NBLK_SCAN, 256, 0, s_csr>>>();
    scatter_k<<<(N_EDGES / 4 + 255) / 256, 256, 0, s_csr>>>(
        (const int4*)esrc, (const int4*)edst, (const float4*)ew);
    cudaEventRecord(ev_csr, s_csr);

    // main chain
    conv_w_k<<<(NFEAT * NHID + NHID * NCLASS + 255) / 256, 256>>>(W1, W2);
    gemm1_fused_k<<<M_PAD / 128, 512, SMEM_G1>>>(x, dB1, dXW1);

    // join: gather needs CSR
    cudaStreamWaitEvent(0, ev_csr, 0);
    spmm1_gemm2_k<<<M_PAD / 128, 256, SMEM_SG>>>(b1, dB2, dHW2);
    spmm2_lsm_k<<<N_NODES / 16, 256>>>(b2, out);
}

// round 14
// speedup vs baseline: 1.3659x; 1.3659x over previous
#include <cuda_runtime.h>
#include <cuda_fp16.h>
#include <cstdint>

#define N_NODES 50000
#define M_PAD   50048      // 391 * 128
#define N_EDGES 800000
#define NFEAT   512
#define NHID    256
#define NCLASS  64
#define NBLK_SCAN 196      // ceil(50000/256)

// ---------------- scratch (static device globals; no runtime allocation) ----
__device__ __align__(256) __half g_B1[(size_t)NHID * NFEAT];     // [n][k] = fp16(W1[k][n])
__device__ __align__(256) __half g_A2[(size_t)M_PAD * NHID];     // 26 MB (H, fp16)
__device__ __align__(256) __half g_B2[(size_t)NCLASS * NHID];    // [n][k] = fp16(W2[k][n])
__device__ __align__(256) __half g_XW1[(size_t)N_NODES * NHID];  // 26 MB
__device__ __align__(256) __half g_HW2[(size_t)N_NODES * NCLASS];// 6.4 MB
__device__ int   g_counts [N_NODES];
__device__ int   g_row_ptr[N_NODES + 1];
__device__ int   g_incl   [N_NODES];
__device__ int   g_blksum [256];
__device__ int   g_perm   [N_EDGES];
__device__ int   g_src_sorted[N_EDGES];
__device__ float g_w_sorted  [N_EDGES];

// ---------------- helpers ---------------------------------------------------
__device__ __forceinline__ uint32_t smem_u32(const void* p) {
    uint32_t a;
    asm("{ .reg .u64 t; cvta.to.shared.u64 t, %1; cvt.u32.u64 %0, t; }"
        : "=r"(a) : "l"(p));
    return a;
}
__device__ __forceinline__ uint32_t pack_h2(__half a, __half b) {
    __half2 p(a, b);
    return *(uint32_t*)&p;
}

// ---------------- CSR build -------------------------------------------------
__global__ void zero_counts_k() {
    int i = blockIdx.x * blockDim.x + threadIdx.x;
    if (i * 4 < N_NODES) *(int4*)(g_counts + i * 4) = make_int4(0, 0, 0, 0);
}

// histogram + record each edge's within-node rank (perm)
__global__ void hist_k(const int4* __restrict__ edst4) {
    int i = blockIdx.x * blockDim.x + threadIdx.x;
    if (i < N_EDGES / 4) {
        int4 d = __ldg(&edst4[i]);
        int p0 = atomicAdd(&g_counts[d.x], 1);
        int p1 = atomicAdd(&g_counts[d.y], 1);
        int p2 = atomicAdd(&g_counts[d.z], 1);
        int p3 = atomicAdd(&g_counts[d.w], 1);
        *(int4*)(g_perm + i * 4) = make_int4(p0, p1, p2, p3);
    }
}

// 3-phase parallel scan of g_counts -> g_row_ptr (exclusive)
__global__ __launch_bounds__(256) void scan_a_k() {
    __shared__ int sh[256];
    int b = blockIdx.x, t = threadIdx.x;
    int i = b * 256 + t;
    int v = (i < N_NODES) ? g_counts[i] : 0;
    sh[t] = v;
    __syncthreads();
    for (int off = 1; off < 256; off <<= 1) {
        int u = (t >= off) ? sh[t - off] : 0;
        __syncthreads();
        sh[t] += u;
        __syncthreads();
    }
    if (i < N_NODES) g_incl[i] = sh[t];
    if (t == 255) g_blksum[b] = sh[255];
}

__global__ __launch_bounds__(256) void scan_b_k() {
    __shared__ int sh[256];
    int t = threadIdx.x;
    sh[t] = (t < NBLK_SCAN) ? g_blksum[t] : 0;
    __syncthreads();
    for (int off = 1; off < 256; off <<= 1) {
        int u = (t >= off) ? sh[t - off] : 0;
        __syncthreads();
        sh[t] += u;
        __syncthreads();
    }
    g_blksum[t] = sh[t];   // inclusive
}

__global__ __launch_bounds__(256) void scan_c_k() {
    int b = blockIdx.x, t = threadIdx.x;
    int i = b * 256 + t;
    if (i < N_NODES) {
        int off = (b == 0) ? 0 : g_blksum[b - 1];
        int incl = g_incl[i] + off;
        g_row_ptr[i] = incl - g_counts[i];
        if (i == N_NODES - 1) g_row_ptr[N_NODES] = incl;
    }
}

// atomic-free scatter using perm
__global__ void scatter_k(const int4* __restrict__ esrc4,
                          const int4* __restrict__ edst4,
                          const float4* __restrict__ ew4) {
    int i = blockIdx.x * blockDim.x + threadIdx.x;
    if (i < N_EDGES / 4) {
        int4   sv = __ldg(&esrc4[i]);
        int4   dv = __ldg(&edst4[i]);
        float4 wv = __ldg(&ew4[i]);
        int4   pv = *(const int4*)(g_perm + i * 4);
        int p0 = __ldg(&g_row_ptr[dv.x]) + pv.x;
        int p1 = __ldg(&g_row_ptr[dv.y]) + pv.y;
        int p2 = __ldg(&g_row_ptr[dv.z]) + pv.z;
        int p3 = __ldg(&g_row_ptr[dv.w]) + pv.w;
        g_src_sorted[p0] = sv.x; g_w_sorted[p0] = wv.x;
        g_src_sorted[p1] = sv.y; g_w_sorted[p1] = wv.y;
        g_src_sorted[p2] = sv.z; g_w_sorted[p2] = wv.z;
        g_src_sorted[p3] = sv.w; g_w_sorted[p3] = wv.w;
    }
}

// ---------------- weight conversions (merged) --------------------------------
__global__ void conv_w_k(const float* __restrict__ W1,
                         const float* __restrict__ W2) {
    int i = blockIdx.x * blockDim.x + threadIdx.x;
    if (i < NFEAT * NHID) {
        int k = i / NHID, n = i - k * NHID;
        g_B1[(size_t)n * NFEAT + k] = __float2half(W1[i]);
    } else if (i < NFEAT * NHID + NHID * NCLASS) {
        int j = i - NFEAT * NHID;
        int k = j / NCLASS, n = j - k * NCLASS;
        g_B2[(size_t)n * NHID + k] = __float2half(W2[j]);
    }
}

// ---------------- GEMM1 fused: XW1 = x @ W1, fp16 single-term ---------------
// BM=128, BN=256 (all columns), 512 threads = 16 warps (4x4), warp tile 32x64.
__global__ __launch_bounds__(512, 1) void gemm1_fused_k(const float* __restrict__ x,
                                                        const __half* __restrict__ B1,
                                                        __half* __restrict__ C) {
    constexpr int STRIDE_B = 80;
    constexpr int NCH = NFEAT / 32;   // 16
    extern __shared__ char smem[];
    uint32_t sa = smem_u32(smem);

    int tid = threadIdx.x, warp = tid >> 5, lane = tid & 31;
    int m0 = blockIdx.x * 128;
    int wm = warp & 3, wn = warp >> 2;
    int wm0 = wm * 32, wn0 = wn * 64;

    int r = tid >> 2, q = tid & 3;
    bool rowok = (m0 + r) < N_NODES;
    const float* xrow = x + (size_t)(m0 + r) * NFEAT + q * 8;

    const char* Bgl = (const char*)B1;

    auto load_B = [&](int c, int buf) {
        uint32_t bb = sa + 10240 + buf * 20480;
#pragma unroll
        for (int u = 0; u < 2; u++) {
            int idx = u * 512 + tid;
            int row = idx >> 2, qq = idx & 3;
            uint32_t dst = bb + row * STRIDE_B + qq * 16;
            const void* src = Bgl + (size_t)row * 1024 + c * 64 + qq * 16;
            asm volatile("cp.async.cg.shared.global [%0], [%1], 16;"
                         :: "r"(dst), "l"(src));
        }
        asm volatile("cp.async.commit_group;");
    };

    float4 pf[2];
#pragma unroll
    for (int j = 0; j < 2; j++)
        pf[j] = rowok ? *(const float4*)(xrow + j * 4)
                      : make_float4(0.f, 0.f, 0.f, 0.f);
    load_B(0, 0);

    float acc[2][8][4];
#pragma unroll
    for (int i = 0; i < 2; i++)
#pragma unroll
        for (int j = 0; j < 8; j++)
#pragma unroll
            for (int p = 0; p < 4; p++) acc[i][j][p] = 0.f;

    for (int c = 0; c < NCH; c++) {
        {
            char* base = smem + r * STRIDE_B + q * 16;
            __half h[8];
#pragma unroll
            for (int j = 0; j < 2; j++) {
                float4 v = pf[j];
                h[j*4+0] = __float2half(v.x);
                h[j*4+1] = __float2half(v.y);
                h[j*4+2] = __float2half(v.z);
                h[j*4+3] = __float2half(v.w);
            }
            uint4 hv = make_uint4(pack_h2(h[0],h[1]), pack_h2(h[2],h[3]),
                                  pack_h2(h[4],h[5]), pack_h2(h[6],h[7]));
            *(uint4*)base = hv;
        }
        if (c + 1 < NCH) {
#pragma unroll
            for (int j = 0; j < 2; j++)
                pf[j] = rowok ? *(const float4*)(xrow + (c + 1) * 32 + j * 4)
                              : make_float4(0.f, 0.f, 0.f, 0.f);
            load_B(c + 1, (c + 1) & 1);
            asm volatile("cp.async.wait_group 1;");
        } else {
            asm volatile("cp.async.wait_group 0;");
        }
        __syncthreads();

        uint32_t aH = sa;
        uint32_t bH = sa + 10240 + (c & 1) * 20480;
#pragma unroll
        for (int kk = 0; kk < 2; kk++) {
            uint32_t af[2][4];
#pragma unroll
            for (int mt = 0; mt < 2; mt++) {
                uint32_t addr = aH + (wm0 + mt * 16 + (lane & 15)) * STRIDE_B
                              + kk * 32 + (lane >> 4) * 16;
                asm volatile(
                    "ldmatrix.sync.aligned.m8n8.x4.shared.b16 {%0,%1,%2,%3}, [%4];"
                    : "=r"(af[mt][0]), "=r"(af[mt][1]),
                      "=r"(af[mt][2]), "=r"(af[mt][3]) : "r"(addr));
            }
#pragma unroll
            for (int nh = 0; nh < 2; nh++) {
                uint32_t bf[4][2];
#pragma unroll
                for (int nb = 0; nb < 2; nb++) {
                    int nrow = wn0 + nh * 32 + nb * 16
                             + (lane & 7) + ((lane >> 4) & 1) * 8;
                    int khalf = (lane >> 3) & 1;
                    uint32_t adH = bH + nrow * STRIDE_B + kk * 32 + khalf * 16;
                    asm volatile(
                        "ldmatrix.sync.aligned.m8n8.x4.shared.b16 {%0,%1,%2,%3}, [%4];"
                        : "=r"(bf[nb * 2][0]), "=r"(bf[nb * 2][1]),
                          "=r"(bf[nb * 2 + 1][0]), "=r"(bf[nb * 2 + 1][1])
                        : "r"(adH));
                }
#pragma unroll
                for (int mt = 0; mt < 2; mt++)
#pragma unroll
                    for (int nt = 0; nt < 4; nt++)
                        asm volatile(
                            "mma.sync.aligned.m16n8k16.row.col.f32.f16.f16.f32 "
                            "{%0,%1,%2,%3}, {%4,%5,%6,%7}, {%8,%9}, {%0,%1,%2,%3};"
                            : "+f"(acc[mt][nh*4+nt][0]), "+f"(acc[mt][nh*4+nt][1]),
                              "+f"(acc[mt][nh*4+nt][2]), "+f"(acc[mt][nh*4+nt][3])
                            : "r"(af[mt][0]), "r"(af[mt][1]),
                              "r"(af[mt][2]), "r"(af[mt][3]),
                              "r"(bf[nt][0]), "r"(bf[nt][1]));
            }
        }
        __syncthreads();
    }

#pragma unroll
    for (int mt = 0; mt < 2; mt++) {
        int r0 = m0 + wm0 + mt * 16 + (lane >> 2);
#pragma unroll
        for (int nt = 0; nt < 8; nt++) {
            int cc = wn0 + nt * 8 + (lane & 3) * 2;
            if (r0 < N_NODES)
                *(uint32_t*)(C + (size_t)r0 * NHID + cc) =
                    pack_h2(__float2half(acc[mt][nt][0]),
                            __float2half(acc[mt][nt][1]));
            if (r0 + 8 < N_NODES)
                *(uint32_t*)(C + (size_t)(r0 + 8) * NHID + cc) =
                    pack_h2(__float2half(acc[mt][nt][2]),
                            __float2half(acc[mt][nt][3]));
        }
    }
}

// ---------------- GEMM2: HW2 = A2 @ B2^T (fp16, K=256, BN=64) ---------------
__global__ __launch_bounds__(256) void gemm2_k(const __half* __restrict__ A,
                                               const __half* __restrict__ Bm,
                                               __half* __restrict__ C) {
    constexpr int BM = 128, BN = 64, BK = 32, KK = NHID;
    constexpr int STRIDE_B = 80;
    constexpr int A_BUF = BM * STRIDE_B;   // 10240
    constexpr int B_BUF = BN * STRIDE_B;   // 5120
    constexpr int NC = KK / BK;            // 8

    __shared__ char smem[2 * (A_BUF + B_BUF)];
    uint32_t sa = smem_u32(smem);
    uint32_t sbB = sa + 2 * A_BUF;

    int tid = threadIdx.x, warp = tid >> 5, lane = tid & 31;
    int m0 = blockIdx.x * BM;
    int wm = warp & 3, wn = warp >> 2;     // 4 x 2
    int wm0 = wm * 32, wn0 = wn * 32;

    const char* Agl = (const char*)(A + (size_t)m0 * KK);
    const char* Bgl = (const char*)Bm;

    auto load_tile = [&](int c, int buf) {
        int koff = c * BK * 2;
        uint32_t ad = sa + buf * A_BUF;
#pragma unroll
        for (int u = 0; u < 2; u++) {
            int idx = u * 256 + tid;
            int r = idx >> 2, ch = idx & 3;
            uint32_t dst = ad + r * STRIDE_B + ch * 16;
            const void* src = Agl + (size_t)r * (KK * 2) + koff + ch * 16;
            asm volatile("cp.async.cg.shared.global [%0], [%1], 16;"
                         :: "r"(dst), "l"(src));
        }
        uint32_t bd = sbB + buf * B_BUF;
        {
            int r = tid >> 2, ch = tid & 3;
            if (r < BN) {
                uint32_t dst = bd + r * STRIDE_B + ch * 16;
                const void* src = Bgl + (size_t)r * (KK * 2) + koff + ch * 16;
                asm volatile("cp.async.cg.shared.global [%0], [%1], 16;"
                             :: "r"(dst), "l"(src));
            }
        }
        asm volatile("cp.async.commit_group;");
    };

    float acc[2][4][4];
#pragma unroll
    for (int i = 0; i < 2; i++)
#pragma unroll
        for (int j = 0; j < 4; j++)
#pragma unroll
            for (int p = 0; p < 4; p++) acc[i][j][p] = 0.f;

    load_tile(0, 0);

    for (int c = 0; c < NC; c++) {
        int buf = c & 1;
        if (c + 1 < NC) {
            load_tile(c + 1, buf ^ 1);
            asm volatile("cp.async.wait_group 1;");
        } else {
            asm volatile("cp.async.wait_group 0;");
        }
        __syncthreads();

        uint32_t abase = sa + buf * A_BUF;
        uint32_t bbase = sbB + buf * B_BUF;
#pragma unroll
        for (int kk = 0; kk < 2; kk++) {
            uint32_t af[2][4];
#pragma unroll
            for (int mt = 0; mt < 2; mt++) {
                uint32_t addr = abase
                    + (wm0 + mt * 16 + (lane & 15)) * STRIDE_B
                    + kk * 32 + (lane >> 4) * 16;
                asm volatile(
                    "ldmatrix.sync.aligned.m8n8.x4.shared.b16 {%0,%1,%2,%3}, [%4];"
                    : "=r"(af[mt][0]), "=r"(af[mt][1]),
                      "=r"(af[mt][2]), "=r"(af[mt][3])
                    : "r"(addr));
            }
            uint32_t bf[4][2];
#pragma unroll
            for (int nb = 0; nb < 2; nb++) {
                int nrow = wn0 + nb * 16 + (lane & 7) + ((lane >> 4) & 1) * 8;
                int khalf = (lane >> 3) & 1;
                uint32_t addr = bbase + nrow * STRIDE_B + kk * 32 + khalf * 16;
                asm volatile(
                    "ldmatrix.sync.aligned.m8n8.x4.shared.b16 {%0,%1,%2,%3}, [%4];"
                    : "=r"(bf[nb * 2][0]), "=r"(bf[nb * 2][1]),
                      "=r"(bf[nb * 2 + 1][0]), "=r"(bf[nb * 2 + 1][1])
                    : "r"(addr));
            }
#pragma unroll
            for (int mt = 0; mt < 2; mt++)
#pragma unroll
                for (int nt = 0; nt < 4; nt++) {
                    asm volatile(
                        "mma.sync.aligned.m16n8k16.row.col.f32.f16.f16.f32 "
                        "{%0,%1,%2,%3}, {%4,%5,%6,%7}, {%8,%9}, {%0,%1,%2,%3};"
                        : "+f"(acc[mt][nt][0]), "+f"(acc[mt][nt][1]),
                          "+f"(acc[mt][nt][2]), "+f"(acc[mt][nt][3])
                        : "r"(af[mt][0]), "r"(af[mt][1]),
                          "r"(af[mt][2]), "r"(af[mt][3]),
                          "r"(bf[nt][0]), "r"(bf[nt][1]));
                }
        }
        __syncthreads();
    }

#pragma unroll
    for (int mt = 0; mt < 2; mt++) {
        int r0 = m0 + wm0 + mt * 16 + (lane >> 2);
#pragma unroll
        for (int nt = 0; nt < 4; nt++) {
            int cc = wn0 + nt * 8 + (lane & 3) * 2;
            if (r0 < N_NODES)
                *(uint32_t*)(C + (size_t)r0 * NCLASS + cc) =
                    pack_h2(__float2half(acc[mt][nt][0]),
                            __float2half(acc[mt][nt][1]));
            if (r0 + 8 < N_NODES)
                *(uint32_t*)(C + (size_t)(r0 + 8) * NCLASS + cc) =
                    pack_h2(__float2half(acc[mt][nt][2]),
                            __float2half(acc[mt][nt][3]));
        }
    }
}

// ---------------- SpMM layer 1: A2 = fp16(relu(A @ XW1 + b1)) ---------------
// 4 nodes per 256-thread block; 64 threads per node, 4 fp16 feats per thread.
__global__ __launch_bounds__(256) void spmm1_k(const float* __restrict__ b1) {
    int t = threadIdx.x;
    int node = blockIdx.x * 4 + (t >> 6);
    int fb = (t & 63) * 4;
    int s = g_row_ptr[node], e = g_row_ptr[node + 1];

    float a0 = 0.f, a1 = 0.f, a2 = 0.f, a3 = 0.f;
    int i = s;
    for (; i + 2 <= e; i += 2) {
        int   s0 = __ldg(&g_src_sorted[i]);
        int   s1 = __ldg(&g_src_sorted[i + 1]);
        float w0 = __ldg(&g_w_sorted[i]);
        float w1 = __ldg(&g_w_sorted[i + 1]);
        uint2 u0 = __ldg((const uint2*)(g_XW1 + (size_t)s0 * NHID + fb));
        uint2 u1 = __ldg((const uint2*)(g_XW1 + (size_t)s1 * NHID + fb));
        float2 p0 = __half22float2(*(__half2*)&u0.x);
        float2 p1 = __half22float2(*(__half2*)&u0.y);
        a0 += w0 * p0.x; a1 += w0 * p0.y; a2 += w0 * p1.x; a3 += w0 * p1.y;
        float2 q0 = __half22float2(*(__half2*)&u1.x);
        float2 q1 = __half22float2(*(__half2*)&u1.y);
        a0 += w1 * q0.x; a1 += w1 * q0.y; a2 += w1 * q1.x; a3 += w1 * q1.y;
    }
    if (i < e) {
        int   s0 = __ldg(&g_src_sorted[i]);
        float w0 = __ldg(&g_w_sorted[i]);
        uint2 u0 = __ldg((const uint2*)(g_XW1 + (size_t)s0 * NHID + fb));
        float2 p0 = __half22float2(*(__half2*)&u0.x);
        float2 p1 = __half22float2(*(__half2*)&u0.y);
        a0 += w0 * p0.x; a1 += w0 * p0.y; a2 += w0 * p1.x; a3 += w0 * p1.y;
    }
    float4 bb = __ldg((const float4*)(b1 + fb));
    float v0 = fmaxf(a0 + bb.x, 0.f);
    float v1 = fmaxf(a1 + bb.y, 0.f);
    float v2 = fmaxf(a2 + bb.z, 0.f);
    float v3 = fmaxf(a3 + bb.w, 0.f);

    uint2 hv = make_uint2(pack_h2(__float2half(v0), __float2half(v1)),
                          pack_h2(__float2half(v2), __float2half(v3)));
    *(uint2*)(g_A2 + (size_t)node * NHID + fb) = hv;
}

// ---------------- SpMM layer 2 fused with bias + log_softmax ----------------
// 16 nodes per 256-thread block; 16 threads per node, 4 fp16 classes each.
__global__ __launch_bounds__(256) void spmm2_lsm_k(const float* __restrict__ b2,
                                                   float* __restrict__ out) {
    int t = threadIdx.x;
    int node = blockIdx.x * 16 + (t >> 4);
    int fb = (t & 15) * 4;
    int s = g_row_ptr[node], e = g_row_ptr[node + 1];

    float a0 = 0.f, a1 = 0.f, a2 = 0.f, a3 = 0.f;
    int i = s;
    for (; i + 2 <= e; i += 2) {
        int   s0 = __ldg(&g_src_sorted[i]);
        int   s1 = __ldg(&g_src_sorted[i + 1]);
        float w0 = __ldg(&g_w_sorted[i]);
        float w1 = __ldg(&g_w_sorted[i + 1]);
        uint2 u0 = __ldg((const uint2*)(g_HW2 + (size_t)s0 * NCLASS + fb));
        uint2 u1 = __ldg((const uint2*)(g_HW2 + (size_t)s1 * NCLASS + fb));
        float2 p0 = __half22float2(*(__half2*)&u0.x);
        float2 p1 = __half22float2(*(__half2*)&u0.y);
        a0 += w0 * p0.x; a1 += w0 * p0.y; a2 += w0 * p1.x; a3 += w0 * p1.y;
        float2 q0 = __half22float2(*(__half2*)&u1.x);
        float2 q1 = __half22float2(*(__half2*)&u1.y);
        a0 += w1 * q0.x; a1 += w1 * q0.y; a2 += w1 * q1.x; a3 += w1 * q1.y;
    }
    if (i < e) {
        int   s0 = __ldg(&g_src_sorted[i]);
        float w0 = __ldg(&g_w_sorted[i]);
        uint2 u0 = __ldg((const uint2*)(g_HW2 + (size_t)s0 * NCLASS + fb));
        float2 p0 = __half22float2(*(__half2*)&u0.x);
        float2 p1 = __half22float2(*(__half2*)&u0.y);
        a0 += w0 * p0.x; a1 += w0 * p0.y; a2 += w0 * p1.x; a3 += w0 * p1.y;
    }
    float4 bb = __ldg((const float4*)(b2 + fb));
    float4 lg = make_float4(a0 + bb.x, a1 + bb.y, a2 + bb.z, a3 + bb.w);

    float m = fmaxf(fmaxf(lg.x, lg.y), fmaxf(lg.z, lg.w));
#pragma unroll
    for (int o = 8; o > 0; o >>= 1)
        m = fmaxf(m, __shfl_xor_sync(0xffffffffu, m, o));

    float ex = __expf(lg.x - m) + __expf(lg.y - m)
             + __expf(lg.z - m) + __expf(lg.w - m);
#pragma unroll
    for (int o = 8; o > 0; o >>= 1)
        ex += __shfl_xor_sync(0xffffffffu, ex, o);

    float lz = m + __logf(ex);
    float4 rr = make_float4(lg.x - lz, lg.y - lz, lg.z - lz, lg.w - lz);
    *(float4*)(out + (size_t)node * NCLASS + fb) = rr;
}

// ---------------- launch ----------------------------------------------------
extern "C" void kernel_launch(void* const* d_in, const int* in_sizes, int n_in,
                              void* d_out, int out_size) {
    const float* x    = (const float*)d_in[0];
    const float* W1   = (const float*)d_in[1];
    const float* b1   = (const float*)d_in[2];
    const float* W2   = (const float*)d_in[3];
    const float* b2   = (const float*)d_in[4];
    const float* ew   = (const float*)d_in[5];
    const int*   esrc = (const int*)d_in[6];
    const int*   edst = (const int*)d_in[7];
    float* out = (float*)d_out;

    __half *dB1, *dA2, *dB2, *dXW1, *dHW2;
    cudaGetSymbolAddress((void**)&dB1, g_B1);
    cudaGetSymbolAddress((void**)&dA2, g_A2);
    cudaGetSymbolAddress((void**)&dB2, g_B2);
    cudaGetSymbolAddress((void**)&dXW1, g_XW1);
    cudaGetSymbolAddress((void**)&dHW2, g_HW2);

    const int SMEM_G1 = 10240 + 2 * 20480;   // 51200
    static bool s_init = false;
    static cudaStream_t s_csr;
    static cudaEvent_t ev_root, ev_csr;
    if (!s_init) {
        cudaFuncSetAttribute(gemm1_fused_k,
                             cudaFuncAttributeMaxDynamicSharedMemorySize, SMEM_G1);
        cudaStreamCreateWithFlags(&s_csr, cudaStreamNonBlocking);
        cudaEventCreateWithFlags(&ev_root, cudaEventDisableTiming);
        cudaEventCreateWithFlags(&ev_csr, cudaEventDisableTiming);
        s_init = true;
    }

    // fork: CSR build on side stream (perm-trick + parallel scan)
    cudaEventRecord(ev_root, 0);
    cudaStreamWaitEvent(s_csr, ev_root, 0);
    zero_counts_k<<<(N_NODES / 4 + 255) / 256, 256, 0, s_csr>>>();
    hist_k<<<(N_EDGES / 4 + 255) / 256, 256, 0, s_csr>>>((const int4*)edst);
    scan_a_k<<<NBLK_SCAN, 256, 0, s_csr>>>();
    scan_b_k<<<1, 256, 0, s_csr>>>();
    scan_c_k<<<NBLK_SCAN, 256, 0, s_csr>>>();
    scatter_k<<<(N_EDGES / 4 + 255) / 256, 256, 0, s_csr>>>(
        (const int4*)esrc, (const int4*)edst, (const float4*)ew);
    cudaEventRecord(ev_csr, s_csr);

    // main chain
    conv_w_k<<<(NFEAT * NHID + NHID * NCLASS + 255) / 256, 256>>>(W1, W2);
    gemm1_fused_k<<<M_PAD / 128, 512, SMEM_G1>>>(x, dB1, dXW1);

    // join: spmm needs CSR
    cudaStreamWaitEvent(0, ev_csr, 0);
    spmm1_k<<<N_NODES / 4, 256>>>(b1);
    gemm2_k<<<M_PAD / 128, 256>>>(dA2, dB2, dHW2);
    spmm2_lsm_k<<<N_NODES / 16, 256>>>(b2, out);
}